// round 4
// baseline (speedup 1.0000x reference)
#include <cuda_runtime.h>
#include <cstdint>

#define B 8
#define T 128
#define NH 8
#define C2 16
#define H 32
#define W 64
#define L 2048
#define DC 32
#define BT 1024
#define BN_EPS 1e-5f

// Scratch (device globals: allocation-free per harness rules)
__device__ float g_cum[(size_t)BT * C2 * H * W];   // cumsum images  (134 MB)
__device__ float g_cov[(size_t)BT * NH * L];       // post-proj vals ( 67 MB)
__device__ float g_sum[NH];
__device__ float g_sumsq[NH];
__device__ float g_mean[NH];
__device__ float g_istd[NH];

// ---------------------------------------------------------------------------
// Kernel A: exclusive cumsum over t, rearrange to per-(b,t) channel images.
// channel c<8 -> prev head c, c>=8 -> curr head c-8.
// Also zeroes the BN stat accumulators.
// ---------------------------------------------------------------------------
__global__ void k_cumsum(const float* __restrict__ prev,
                         const float* __restrict__ curr) {
    int idx = blockIdx.x * blockDim.x + threadIdx.x;   // [0, B*C2*L)
    if (blockIdx.x == 0 && threadIdx.x < NH) {
        g_sum[threadIdx.x] = 0.f;
        g_sumsq[threadIdx.x] = 0.f;
    }
    int l = idx & (L - 1);
    int c = (idx >> 11) & 15;
    int b = idx >> 15;
    const float* src = (c < NH ? prev : curr) + ((size_t)(b * NH + (c & 7)) * T) * L + l;
    float* dst = g_cum + ((size_t)(b * T) * C2 + c) * L + l;
    float s = 0.f;
    #pragma unroll 4
    for (int t = 0; t < T; t++) {
        *dst = s;
        s += *src;
        src += L;
        dst += C2 * L;
    }
}

// ---------------------------------------------------------------------------
// Kernel B: 5x5 conv (16->32) + bias + relu + mask + 1x1 proj (32->8)
//           + BN statistics accumulation.
// CTA: one (b,t) image, 8-row stripe (8x64 = 512 px). 256 threads.
// Thread: 4 contiguous pixels x 16 out-channels, accumulated as 8 f32x2 pairs.
// ---------------------------------------------------------------------------
#define SIN_CI 816                 // 12*68 floats per channel
#define SMEM_W_OFF   52224         // after 16*12*68*4 input tile
#define SMEM_PROJ_OFF 103424       // after 400*16*8 weight pairs
#define SMEM_STAT_OFF 104448
#define SMEM_TOTAL   104512
#define COVP 33                    // padded pitch for 32-ch staging buffer

__global__ __launch_bounds__(256, 2)
void k_conv(const float* __restrict__ conv_w, const float* __restrict__ conv_b,
            const float* __restrict__ proj_w, const unsigned int* __restrict__ mask) {
    extern __shared__ char smem[];
    float*  s_in   = (float*)smem;                       // [16][12][68]
    float2* s_w    = (float2*)(smem + SMEM_W_OFF);       // [400][16] co-pairs
    float*  s_cov  = (float*)smem;                       // [512][33] (reuses s_in/s_w)
    float*  s_proj = (float*)(smem + SMEM_PROJ_OFF);     // [8][32]
    float*  s_stat = (float*)(smem + SMEM_STAT_OFF);     // [16]

    const int tid = threadIdx.x;
    const int bt  = blockIdx.x;
    const int y0  = blockIdx.y * 8;
    const int b   = bt >> 7;

    // --- load paired weights: s_w[k][cp] with k = (ky*5+kx)*16 + ci ---
    for (int i = tid; i < 6400; i += 256) {
        int cp  = i & 15;
        int k   = i >> 4;
        int ci  = k & 15;
        int kyx = k >> 4;                 // ky*5+kx
        int widx = ci * 25 + kyx;         // conv_w[d][ci][ky][kx]
        float2 wv;
        wv.x = conv_w[(2 * cp) * 400 + widx];
        wv.y = conv_w[(2 * cp + 1) * 400 + widx];
        s_w[k * 16 + cp] = wv;
    }

    // --- load input tile with halo (zero-padded) ---
    for (int i = tid; i < 16 * 12 * 68; i += 256) {
        int x   = i % 68;
        int rem = i / 68;
        int y   = rem % 12;
        int ci  = rem / 12;
        int gy  = y0 + y - 2;
        int gx  = x - 2;
        float v = 0.f;
        if ((unsigned)gy < H && (unsigned)gx < W)
            v = g_cum[(((size_t)bt * C2 + ci) * H + gy) * W + gx];
        s_in[ci * SIN_CI + y * 68 + x] = v;
    }

    if (tid < 256) s_proj[tid] = proj_w[tid];   // (8,32,1,1) -> 256 floats
    if (tid < 16)  s_stat[tid] = 0.f;
    __syncthreads();

    // --- conv main loop ---
    const int group = tid >> 7;          // 0: co 0..15, 1: co 16..31
    const int g     = tid & 127;
    const int r     = g >> 4;            // 0..7 rows
    const int xb    = (g & 15) * 4;      // 4 contiguous pixels
    const int cpb   = group * 8;         // co-pair base

    unsigned long long acc[4][8];
    #pragma unroll
    for (int p = 0; p < 8; p++) {
        float b0 = conv_b[(cpb + p) * 2];
        float b1 = conv_b[(cpb + p) * 2 + 1];
        unsigned long long bb;
        asm("mov.b64 %0, {%1, %2};" : "=l"(bb) : "f"(b0), "f"(b1));
        #pragma unroll
        for (int i = 0; i < 4; i++) acc[i][p] = bb;
    }

    #pragma unroll 1
    for (int ky = 0; ky < 5; ky++) {
        const float* inrow = s_in + (r + ky) * 68 + xb;
        #pragma unroll 1
        for (int kx = 0; kx < 5; kx++) {
            const float* ip = inrow + kx;
            const unsigned long long* wp =
                (const unsigned long long*)(s_w + (ky * 5 + kx) * 256 + cpb);
            #pragma unroll 8
            for (int ci = 0; ci < 16; ci++) {
                float v0 = ip[ci * SIN_CI + 0];
                float v1 = ip[ci * SIN_CI + 1];
                float v2 = ip[ci * SIN_CI + 2];
                float v3 = ip[ci * SIN_CI + 3];
                unsigned long long vv0, vv1, vv2, vv3;
                asm("mov.b64 %0, {%1, %1};" : "=l"(vv0) : "f"(v0));
                asm("mov.b64 %0, {%1, %1};" : "=l"(vv1) : "f"(v1));
                asm("mov.b64 %0, {%1, %1};" : "=l"(vv2) : "f"(v2));
                asm("mov.b64 %0, {%1, %1};" : "=l"(vv3) : "f"(v3));
                const unsigned long long* wk = wp + ci * 16;
                #pragma unroll
                for (int p = 0; p < 8; p++) {
                    unsigned long long wv = wk[p];
                    asm("fma.rn.f32x2 %0, %1, %2, %0;" : "+l"(acc[0][p]) : "l"(vv0), "l"(wv));
                    asm("fma.rn.f32x2 %0, %1, %2, %0;" : "+l"(acc[1][p]) : "l"(vv1), "l"(wv));
                    asm("fma.rn.f32x2 %0, %1, %2, %0;" : "+l"(acc[2][p]) : "l"(vv2), "l"(wv));
                    asm("fma.rn.f32x2 %0, %1, %2, %0;" : "+l"(acc[3][p]) : "l"(vv3), "l"(wv));
                }
            }
        }
    }

    // --- stage relu'd 32-ch values to smem (overwrites s_in/s_w) ---
    __syncthreads();
    #pragma unroll
    for (int i = 0; i < 4; i++) {
        int px = r * 64 + xb + i;
        #pragma unroll
        for (int p = 0; p < 8; p++) {
            float lo, hi;
            asm("mov.b64 {%0, %1}, %2;" : "=f"(lo), "=f"(hi) : "l"(acc[i][p]));
            s_cov[px * COVP + (cpb + p) * 2]     = fmaxf(lo, 0.f);
            s_cov[px * COVP + (cpb + p) * 2 + 1] = fmaxf(hi, 0.f);
        }
    }
    __syncthreads();

    // --- mask + 1x1 proj + stats + store ---
    float lsum[8], lsq[8];
    #pragma unroll
    for (int n = 0; n < 8; n++) { lsum[n] = 0.f; lsq[n] = 0.f; }

    #pragma unroll
    for (int q = 0; q < 2; q++) {
        int px = tid + q * 256;
        int y = px >> 6, x = px & 63;
        int l = (y0 + y) * 64 + x;
        bool m = mask[b * L + l] != 0u;        // robust: int32 or f32 encoding
        const float* cv = s_cov + px * COVP;
        #pragma unroll
        for (int n = 0; n < 8; n++) {
            float s = 0.f;
            #pragma unroll
            for (int d = 0; d < 32; d++) s = fmaf(cv[d], s_proj[n * 32 + d], s);
            s = m ? 0.f : s;
            lsum[n] += s;
            lsq[n]  += s * s;
            g_cov[(((size_t)bt) * NH + n) * L + l] = s;
        }
    }

    // warp reduce, then shared, then global atomics
    #pragma unroll
    for (int n = 0; n < 8; n++) {
        #pragma unroll
        for (int off = 16; off; off >>= 1) {
            lsum[n] += __shfl_xor_sync(0xFFFFFFFFu, lsum[n], off);
            lsq[n]  += __shfl_xor_sync(0xFFFFFFFFu, lsq[n],  off);
        }
    }
    if ((tid & 31) == 0) {
        #pragma unroll
        for (int n = 0; n < 8; n++) {
            atomicAdd(&s_stat[n], lsum[n]);
            atomicAdd(&s_stat[8 + n], lsq[n]);
        }
    }
    __syncthreads();
    if (tid < 8) {
        atomicAdd(&g_sum[tid],   s_stat[tid]);
        atomicAdd(&g_sumsq[tid], s_stat[8 + tid]);
    }
}

// ---------------------------------------------------------------------------
// Kernel C: finalize BN statistics (single block).
// ---------------------------------------------------------------------------
__global__ void k_finalize(const unsigned int* __restrict__ mask) {
    __shared__ int red[256];
    int tid = threadIdx.x;
    int c = 0;
    for (int i = tid; i < B * L; i += 256) c += (mask[i] == 0u);
    red[tid] = c;
    __syncthreads();
    for (int s = 128; s > 0; s >>= 1) {
        if (tid < s) red[tid] += red[tid + s];
        __syncthreads();
    }
    if (tid < NH) {
        float cnt  = fmaxf((float)red[0] * (float)T, 1.f);
        float mean = g_sum[tid] / cnt;
        float var  = g_sumsq[tid] / cnt - mean * mean;
        var = fmaxf(var, 0.f);
        g_mean[tid] = mean;
        g_istd[tid] = rsqrtf(var + BN_EPS);
    }
}

// ---------------------------------------------------------------------------
// Kernel D: apply BN (unmasked) / zero (masked), transpose to (b*n, t, l).
// ---------------------------------------------------------------------------
__global__ void k_apply(const unsigned int* __restrict__ mask,
                        const float* __restrict__ gamma,
                        const float* __restrict__ beta,
                        float* __restrict__ out) {
    int idx = blockIdx.x * 256 + threadIdx.x;          // [0, 2^24)
    int p  = idx & (L - 1);
    int t  = (idx >> 11) & (T - 1);
    int bn = idx >> 18;
    int b  = bn >> 3, n = bn & 7;
    float v = g_cov[(((size_t)(b * T + t)) * NH + n) * L + p];
    float r;
    if (mask[b * L + p] != 0u) {
        r = 0.f;                                        // masked positions are 0
    } else {
        r = gamma[n] * (v - g_mean[n]) * g_istd[n] + beta[n];
    }
    out[idx] = r;
}

// ---------------------------------------------------------------------------
extern "C" void kernel_launch(void* const* d_in, const int* in_sizes, int n_in,
                              void* d_out, int out_size) {
    const float*        prev = (const float*)d_in[0];
    const float*        curr = (const float*)d_in[1];
    const unsigned int* mask = (const unsigned int*)d_in[2];
    // The last 5 inputs are always conv_w, conv_b, proj_w, gamma, beta —
    // robust to whether the scalar `h` is materialized as a buffer or not.
    int base = n_in - 5;
    const float* conv_w = (const float*)d_in[base];
    const float* conv_b = (const float*)d_in[base + 1];
    const float* proj_w = (const float*)d_in[base + 2];
    const float* gamma  = (const float*)d_in[base + 3];
    const float* beta   = (const float*)d_in[base + 4];
    float*       out    = (float*)d_out;

    cudaFuncSetAttribute(k_conv, cudaFuncAttributeMaxDynamicSharedMemorySize, SMEM_TOTAL);

    k_cumsum<<<1024, 256>>>(prev, curr);
    dim3 gB(BT, 4);
    k_conv<<<gB, 256, SMEM_TOTAL>>>(conv_w, conv_b, proj_w, mask);
    k_finalize<<<1, 256>>>(mask);
    k_apply<<<65536, 256>>>(mask, gamma, beta, out);
}

// round 9
// speedup vs baseline: 2.1673x; 2.1673x over previous
#include <cuda_runtime.h>
#include <cuda_bf16.h>
#include <cstdint>

#define B 8
#define T 128
#define NH 8
#define C2 16
#define H 32
#define W 64
#define L 2048
#define BT 1024
#define BN_EPS 1e-5f

// ---------------------------------------------------------------------------
// Device scratch (no allocations allowed)
// ---------------------------------------------------------------------------
__device__ unsigned int g_cum[(size_t)BT * C2 * H * W]; // packed {bf16 hi | bf16 lo<<16}
__device__ float g_cov[(size_t)BT * NH * L];
__device__ unsigned int g_bw[25 * 2 * 8 * 32];          // B-frag words, XOR-swizzled
__device__ float g_sum[NH];
__device__ float g_sumsq[NH];
__device__ float g_mean[NH];
__device__ float g_istd[NH];

// ---------------------------------------------------------------------------
// mma.sync m16n8k16 bf16 (baseline sm_100-legal HMMA)
// ---------------------------------------------------------------------------
__device__ __forceinline__ void mma_bf16(float* c,
                                         unsigned a0, unsigned a1, unsigned a2, unsigned a3,
                                         unsigned b0, unsigned b1) {
    asm volatile(
        "mma.sync.aligned.m16n8k16.row.col.f32.bf16.bf16.f32 "
        "{%0,%1,%2,%3}, {%4,%5,%6,%7}, {%8,%9}, {%0,%1,%2,%3};"
        : "+f"(c[0]), "+f"(c[1]), "+f"(c[2]), "+f"(c[3])
        : "r"(a0), "r"(a1), "r"(a2), "r"(a3), "r"(b0), "r"(b1));
}

// ---------------------------------------------------------------------------
// Kernel A: exclusive cumsum over t -> packed {bf16 hi, bf16 lo} per value.
// ---------------------------------------------------------------------------
__global__ void k_cumsum(const float* __restrict__ prev,
                         const float* __restrict__ curr) {
    int idx = blockIdx.x * blockDim.x + threadIdx.x;   // [0, B*C2*L)
    if (blockIdx.x == 0 && threadIdx.x < NH) {
        g_sum[threadIdx.x] = 0.f;
        g_sumsq[threadIdx.x] = 0.f;
    }
    int l = idx & (L - 1);
    int c = (idx >> 11) & 15;
    int b = idx >> 15;
    const float* src = (c < NH ? prev : curr) + ((size_t)(b * NH + (c & 7)) * T) * L + l;
    unsigned int* dst = g_cum + ((size_t)(b * T) * C2 + c) * L + l;
    float s = 0.f;
    #pragma unroll 4
    for (int t = 0; t < T; t++) {
        __nv_bfloat16 hi = __float2bfloat16(s);
        float r = s - __bfloat162float(hi);
        __nv_bfloat16 lo = __float2bfloat16(r);
        unsigned int hb = (unsigned int)(*(unsigned short*)&hi);
        unsigned int lb = (unsigned int)(*(unsigned short*)&lo);
        *dst = hb | (lb << 16);
        s += *src;
        src += L;
        dst += C2 * L;
    }
}

// ---------------------------------------------------------------------------
// Kernel P: build B-fragment weight words.
// word[((o*2+s)*8 + j)*32 + (co ^ (8*(j&3)))] = bf16(w[k=2j][co]) | bf16(w[2j+1][co])<<16
// where w[ci][co] is the (hi|lo split s) bf16 of conv_w[co][ci][o/5][o%5].
// ---------------------------------------------------------------------------
__global__ void k_prep(const float* __restrict__ conv_w) {
    for (int i = threadIdx.x; i < 25 * 2 * 8 * 32; i += blockDim.x) {
        int co = i & 31;
        int j  = (i >> 5) & 7;
        int s  = (i >> 8) & 1;
        int o  = i >> 9;
        float w0 = conv_w[co * 400 + (2 * j) * 25 + o];
        float w1 = conv_w[co * 400 + (2 * j + 1) * 25 + o];
        unsigned short h0, h1;
        if (s == 0) {
            __nv_bfloat16 b0 = __float2bfloat16(w0);
            __nv_bfloat16 b1 = __float2bfloat16(w1);
            h0 = *(unsigned short*)&b0; h1 = *(unsigned short*)&b1;
        } else {
            __nv_bfloat16 t0 = __float2bfloat16(w0);
            __nv_bfloat16 t1 = __float2bfloat16(w1);
            __nv_bfloat16 b0 = __float2bfloat16(w0 - __bfloat162float(t0));
            __nv_bfloat16 b1 = __float2bfloat16(w1 - __bfloat162float(t1));
            h0 = *(unsigned short*)&b0; h1 = *(unsigned short*)&b1;
        }
        g_bw[((o * 2 + s) * 8 + j) * 32 + (co ^ (8 * (j & 3)))] =
            (unsigned)h0 | ((unsigned)h1 << 16);
    }
}

// ---------------------------------------------------------------------------
// Kernel B: HMMA conv + bias + relu + mask + 1x1 proj + BN stats.
// CTA: 256 threads / 8 warps; one (b,t) image x 4 rows (256 px).
// Warp: 32 px x 32 co via 2 M16-tiles x 4 N8-tiles of m16n8k16.
// ---------------------------------------------------------------------------
#define PS 548                         // s_in plane stride (words): 548%16==4 -> conflict-free
#define SO_STAT 0
#define SO_BIAS 64
#define SO_PROJ 192
#define SO_IN   1216                   // 16 planes * 548 words (last plane 544 used)
#define SO_BW   36352                  // 25*2*8*32 words = 51200 B
#define SMEM_TOTAL (36352 + 51200)

__global__ __launch_bounds__(256)
void k_conv(const float* __restrict__ conv_b, const float* __restrict__ proj_w,
            const unsigned int* __restrict__ mask) {
    extern __shared__ char smem[];
    float*        s_stat = (float*)(smem + SO_STAT);
    float*        s_bias = (float*)(smem + SO_BIAS);
    float*        s_proj = (float*)(smem + SO_PROJ);
    unsigned int* s_in   = (unsigned int*)(smem + SO_IN);
    unsigned int* s_bw   = (unsigned int*)(smem + SO_BW);

    const int tid = threadIdx.x;
    const int wid = tid >> 5;
    const int lid = tid & 31;
    const int g   = lid >> 2;
    const int tig = lid & 3;
    const int bt  = blockIdx.y;
    const int y0  = blockIdx.x * 4;
    const int b   = bt >> 7;

    if (tid < 16) s_stat[tid] = 0.f;
    if (tid < 32) s_bias[tid] = conv_b[tid];
    s_proj[tid] = proj_w[tid];

    // B-frag words (51200 B)
    {
        const uint4* src = (const uint4*)g_bw;
        uint4* dst = (uint4*)s_bw;
        for (int i = tid; i < 51200 / 16; i += 256) dst[i] = src[i];
    }
    // input tile with halo: rows y0-2..y0+5, cols -2..65, plane stride PS
    for (int i = tid; i < 16 * 8 * 68; i += 256) {
        int x   = i % 68;
        int rem = i / 68;
        int y   = rem & 7;
        int ci  = rem >> 3;
        int gy  = y0 + y - 2;
        int gx  = x - 2;
        unsigned int v = 0;
        if ((unsigned)gy < H && (unsigned)gx < W)
            v = g_cum[(((size_t)bt * C2 + ci) * H + gy) * W + gx];
        s_in[ci * PS + y * 68 + x] = v;
    }
    __syncthreads();

    const int yl = wid >> 1;                // image row within 4-row block
    const int xb = (wid & 1) * 32;          // x base of warp's 32 px

    float acc[2][4][4];
    #pragma unroll
    for (int mt = 0; mt < 2; mt++)
        #pragma unroll
        for (int i = 0; i < 4; i++)
            #pragma unroll
            for (int q = 0; q < 4; q++) acc[mt][i][q] = 0.f;

    #pragma unroll 1
    for (int ky = 0; ky < 5; ky++) {
        #pragma unroll
        for (int kx = 0; kx < 5; kx++) {
            const int o = ky * 5 + kx;
            const unsigned int* bw = s_bw + o * 512;
            // B fragments (hi & lo splits), conflict-free via XOR swizzle
            unsigned bh[4][2], bl[4][2];
            #pragma unroll
            for (int i = 0; i < 4; i++) {
                int csw = (8 * i + g) ^ (8 * tig);
                bh[i][0] = bw[tig * 32 + csw];
                bh[i][1] = bw[(tig + 4) * 32 + csw];
                bl[i][0] = bw[256 + tig * 32 + csw];
                bl[i][1] = bw[256 + (tig + 4) * 32 + csw];
            }
            #pragma unroll
            for (int mt = 0; mt < 2; mt++) {
                int base = (2 * tig) * PS + (yl + ky) * 68 + xb + mt * 16 + kx + g;
                unsigned w00 = s_in[base],            w01 = s_in[base + PS];
                unsigned w10 = s_in[base + 8],        w11 = s_in[base + PS + 8];
                unsigned w20 = s_in[base + 8 * PS],   w21 = s_in[base + 9 * PS];
                unsigned w30 = s_in[base + 8 * PS + 8], w31 = s_in[base + 9 * PS + 8];
                unsigned ah0 = __byte_perm(w00, w01, 0x5410);
                unsigned ah1 = __byte_perm(w10, w11, 0x5410);
                unsigned ah2 = __byte_perm(w20, w21, 0x5410);
                unsigned ah3 = __byte_perm(w30, w31, 0x5410);
                unsigned al0 = __byte_perm(w00, w01, 0x7632);
                unsigned al1 = __byte_perm(w10, w11, 0x7632);
                unsigned al2 = __byte_perm(w20, w21, 0x7632);
                unsigned al3 = __byte_perm(w30, w31, 0x7632);
                #pragma unroll
                for (int i = 0; i < 4; i++) {
                    mma_bf16(acc[mt][i], ah0, ah1, ah2, ah3, bh[i][0], bh[i][1]);
                    mma_bf16(acc[mt][i], al0, al1, al2, al3, bh[i][0], bh[i][1]);
                    mma_bf16(acc[mt][i], ah0, ah1, ah2, ah3, bl[i][0], bl[i][1]);
                }
            }
        }
    }

    // --- epilogue: bias + relu + 1x1 proj (register, tig-group reduce) ---
    float pp[4][8];
    #pragma unroll
    for (int p = 0; p < 4; p++)
        #pragma unroll
        for (int n = 0; n < 8; n++) pp[p][n] = 0.f;

    #pragma unroll
    for (int mt = 0; mt < 2; mt++) {
        #pragma unroll
        for (int r = 0; r < 2; r++) {
            int pidx = mt * 2 + r;
            #pragma unroll
            for (int i = 0; i < 4; i++) {
                int co0 = 8 * i + 2 * tig;
                float v0 = fmaxf(acc[mt][i][2 * r]     + s_bias[co0],     0.f);
                float v1 = fmaxf(acc[mt][i][2 * r + 1] + s_bias[co0 + 1], 0.f);
                #pragma unroll
                for (int n = 0; n < 8; n++)
                    pp[pidx][n] += v0 * s_proj[n * 32 + co0] + v1 * s_proj[n * 32 + co0 + 1];
            }
        }
    }
    // reduce over tig group (lanes xor 1, 2) -> every lane holds full proj
    #pragma unroll
    for (int p = 0; p < 4; p++)
        #pragma unroll
        for (int n = 0; n < 8; n++) {
            pp[p][n] += __shfl_xor_sync(0xFFFFFFFFu, pp[p][n], 1);
            pp[p][n] += __shfl_xor_sync(0xFFFFFFFFu, pp[p][n], 2);
        }

    // mask + store + stats
    float lsum[8], lsq[8];
    #pragma unroll
    for (int n = 0; n < 8; n++) { lsum[n] = 0.f; lsq[n] = 0.f; }

    #pragma unroll
    for (int mt = 0; mt < 2; mt++) {
        #pragma unroll
        for (int r = 0; r < 2; r++) {
            int pidx = mt * 2 + r;
            int l = (y0 + yl) * 64 + xb + mt * 16 + 8 * r + g;
            bool m = mask[b * L + l] != 0u;
            #pragma unroll
            for (int n = 0; n < 8; n++) {
                float s = m ? 0.f : pp[pidx][n];
                lsum[n] += s;
                lsq[n]  += s * s;
                if (tig == 0)
                    g_cov[(((size_t)bt) * NH + n) * L + l] = s;
            }
        }
    }
    // reduce stats over g (xor 4,8,16); every tig-class holds the same totals
    #pragma unroll
    for (int n = 0; n < 8; n++) {
        #pragma unroll
        for (int off = 4; off <= 16; off <<= 1) {
            lsum[n] += __shfl_xor_sync(0xFFFFFFFFu, lsum[n], off);
            lsq[n]  += __shfl_xor_sync(0xFFFFFFFFu, lsq[n],  off);
        }
    }
    if (lid == 0) {
        #pragma unroll
        for (int n = 0; n < 8; n++) {
            atomicAdd(&s_stat[n], lsum[n]);
            atomicAdd(&s_stat[8 + n], lsq[n]);
        }
    }
    __syncthreads();
    if (tid < 8) {
        atomicAdd(&g_sum[tid],   s_stat[tid]);
        atomicAdd(&g_sumsq[tid], s_stat[8 + tid]);
    }
}

// ---------------------------------------------------------------------------
// Kernel C: finalize BN statistics.
// ---------------------------------------------------------------------------
__global__ void k_finalize(const unsigned int* __restrict__ mask) {
    __shared__ int red[256];
    int tid = threadIdx.x;
    int c = 0;
    for (int i = tid; i < B * L; i += 256) c += (mask[i] == 0u);
    red[tid] = c;
    __syncthreads();
    for (int s = 128; s > 0; s >>= 1) {
        if (tid < s) red[tid] += red[tid + s];
        __syncthreads();
    }
    if (tid < NH) {
        float cnt  = fmaxf((float)red[0] * (float)T, 1.f);
        float mean = g_sum[tid] / cnt;
        float var  = g_sumsq[tid] / cnt - mean * mean;
        var = fmaxf(var, 0.f);
        g_mean[tid] = mean;
        g_istd[tid] = rsqrtf(var + BN_EPS);
    }
}

// ---------------------------------------------------------------------------
// Kernel D: apply BN / zero, transpose to (b*n, t, l).
// ---------------------------------------------------------------------------
__global__ void k_apply(const unsigned int* __restrict__ mask,
                        const float* __restrict__ gamma,
                        const float* __restrict__ beta,
                        float* __restrict__ out) {
    int idx = blockIdx.x * 256 + threadIdx.x;
    int p  = idx & (L - 1);
    int t  = (idx >> 11) & (T - 1);
    int bn = idx >> 18;
    int b  = bn >> 3, n = bn & 7;
    float v = g_cov[(((size_t)(b * T + t)) * NH + n) * L + p];
    float r;
    if (mask[b * L + p] != 0u) {
        r = 0.f;
    } else {
        r = gamma[n] * (v - g_mean[n]) * g_istd[n] + beta[n];
    }
    out[idx] = r;
}

// ---------------------------------------------------------------------------
extern "C" void kernel_launch(void* const* d_in, const int* in_sizes, int n_in,
                              void* d_out, int out_size) {
    const float*        prev = (const float*)d_in[0];
    const float*        curr = (const float*)d_in[1];
    const unsigned int* mask = (const unsigned int*)d_in[2];
    int base = n_in - 5;
    const float* conv_w = (const float*)d_in[base];
    const float* conv_b = (const float*)d_in[base + 1];
    const float* proj_w = (const float*)d_in[base + 2];
    const float* gamma  = (const float*)d_in[base + 3];
    const float* beta   = (const float*)d_in[base + 4];
    float*       out    = (float*)d_out;

    cudaFuncSetAttribute(k_conv, cudaFuncAttributeMaxDynamicSharedMemorySize, SMEM_TOTAL);

    k_cumsum<<<1024, 256>>>(prev, curr);
    k_prep<<<1, 256>>>(conv_w);
    dim3 gB(8, 1024);                      // 8 row-blocks x 1024 (b,t) images
    k_conv<<<gB, 256, SMEM_TOTAL>>>(conv_b, proj_w, mask);
    k_finalize<<<1, 256>>>(mask);
    k_apply<<<65536, 256>>>(mask, gamma, beta, out);
}